// round 10
// baseline (speedup 1.0000x reference)
#include <cuda_runtime.h>
#include <cstdint>

// DynamicDownsampling: out[b,c,h,w] = softmax_p(kernel[b,p,h,w]) . x_edgepad 5x5
// Warp-autonomous version: each warp owns a 16x8 output tile with a private
// 4-deep cp.async channel ring. NO __syncthreads anywhere -- per-warp
// wait_group + __syncwarp only. 2x2 quad/lane (36B smem/output), even taps
// packed fma.f32x2 on aligned LDS.64, odd taps scalar FFMA on register halves.

#define KS   5
#define PAD  2
#define KK   25
#define H    256
#define W    256
#define C    32
#define B    4
#define HW   (H*W)

#define WTX  16                   // per-warp output tile width
#define WTY  8                    // per-warp output tile height
#define SROWS 12                  // staged rows (8 + 2*PAD)
#define SCOLM 24                  // padded slab width (floats); data cols 4..19, halo 2,3,20,21
#define SLAB_F (SROWS*SCOLM)      // 288 floats
#define SLAB_B (SLAB_F*4)         // 1152 bytes
#define NBUF 4
#define PREF 3

#define NWARPS 4
#define NTHREADS (NWARPS*32)      // block covers 32x16 via 2x2 warps

typedef unsigned long long ull;

__device__ __forceinline__ uint32_t smem_u32(const void* p) {
    uint32_t a;
    asm("{ .reg .u64 t; cvta.to.shared.u64 t, %1; cvt.u32.u64 %0, t; }" : "=r"(a) : "l"(p));
    return a;
}
__device__ __forceinline__ void cp_async16(uint32_t dst, const float* src) {
    asm volatile("cp.async.cg.shared.global [%0], [%1], 16;\n" :: "r"(dst), "l"(src));
}
__device__ __forceinline__ void cp_async4(uint32_t dst, const float* src) {
    asm volatile("cp.async.ca.shared.global [%0], [%1], 4;\n" :: "r"(dst), "l"(src));
}
__device__ __forceinline__ void cp_commit() { asm volatile("cp.async.commit_group;\n"); }
template<int N> __device__ __forceinline__ void cp_wait() {
    asm volatile("cp.async.wait_group %0;\n" :: "n"(N));
}
__device__ __forceinline__ ull fma2(ull a, ull b, ull c) {
    ull d;
    asm("fma.rn.f32x2 %0, %1, %2, %3;" : "=l"(d) : "l"(a), "l"(b), "l"(c));
    return d;
}
__device__ __forceinline__ ull pack2(float lo, float hi) {
    ull r;
    asm("mov.b64 %0, {%1, %2};" : "=l"(r) : "f"(lo), "f"(hi));
    return r;
}
__device__ __forceinline__ float lo2(ull v) { float a, b; asm("mov.b64 {%0,%1}, %2;" : "=f"(a), "=f"(b) : "l"(v)); return a; }
__device__ __forceinline__ float hi2(ull v) { float a, b; asm("mov.b64 {%0,%1}, %2;" : "=f"(a), "=f"(b) : "l"(v)); return b; }

__global__ __launch_bounds__(NTHREADS, 3)
void dds_kernel(const float* __restrict__ x,
                const float* __restrict__ kern,
                float* __restrict__ out)
{
    __shared__ float slab[NWARPS][NBUF][SLAB_F];   // 18432 B

    const int tid = threadIdx.x;
    const int w   = tid >> 5;          // warp id 0..3
    const int l   = tid & 31;          // lane
    const int wx  = w & 1;
    const int wy  = w >> 1;
    const int qx  = l & 7;             // quad col (2 px), 0..7
    const int qy  = l >> 3;            // quad row (2 px), 0..3

    const int bx = blockIdx.x, by = blockIdx.y, b = blockIdx.z;
    const int x0w = bx * 32 + wx * WTX;        // warp tile origin
    const int y0w = by * 16 + wy * WTY;

    const float* xb = x   + (size_t)b * C * HW;
    float*       ob = out + (size_t)b * C * HW;

    // ---- per-lane staging slots: 3 per channel (96 slots = 12 rows x 8) ----
    // slot s = j*32 + l;  r = s/8 (= 4j + l/8),  k = s%8 (= l&7)
    // k<4: 16B interior (cols 4+4k..7+4k <- gmem x0w+4k, aligned); k>=4: scalar halo
    int soff[PREF]; uint32_t doff[PREF]; bool is16[PREF];
    #pragma unroll
    for (int j = 0; j < PREF; ++j) {
        const int r = 4 * j + (l >> 3);
        const int k = l & 7;
        int yy = y0w - PAD + r;  yy = yy < 0 ? 0 : (yy > H-1 ? H-1 : yy);
        if (k < 4) {
            is16[j] = true;
            soff[j] = yy * W + x0w + 4 * k;                 // always in-range, 16B aligned
            doff[j] = (uint32_t)(r * (SCOLM*4) + 16 + 16 * k);
        } else {
            is16[j] = false;
            const int k2 = k - 4;
            const int scol = (k2 < 2) ? (2 + k2) : (18 + k2);      // 2,3,20,21
            int gx = x0w + ((k2 < 2) ? (k2 - 2) : (14 + k2));      // -2,-1,16,17
            gx = gx < 0 ? 0 : (gx > W-1 ? W-1 : gx);
            soff[j] = yy * W + gx;
            doff[j] = (uint32_t)(r * (SCOLM*4) + scol * 4);
        }
    }

    float* const slab_w = &slab[w][0][0];
    const uint32_t sbase = smem_u32(slab_w);

    // ---- prologue: prefetch channels 0..2 (overlaps weight softmax) ----
    #pragma unroll
    for (int c0 = 0; c0 < PREF; ++c0) {
        const float* src = xb + (size_t)c0 * HW;
        const uint32_t db = sbase + (uint32_t)c0 * SLAB_B;
        #pragma unroll
        for (int j = 0; j < PREF; ++j) {
            if (is16[j]) cp_async16(db + doff[j], src + soff[j]);
            else         cp_async4 (db + doff[j], src + soff[j]);
        }
        cp_commit();
    }

    // ---- softmax weights for the 2x2 quad, packed (col0,col1) per tap ----
    const int gx0 = x0w + 2 * qx;
    const int gy0 = y0w + 2 * qy;
    const float2* kp = (const float2*)(kern + ((size_t)b * KK) * HW + (size_t)gy0 * W + gx0);

    ull wv0[KK], wv1[KK];
    float m00 = -1e30f, m01 = -1e30f, m10 = -1e30f, m11 = -1e30f;
    #pragma unroll
    for (int p = 0; p < KK; ++p) {
        float2 a = kp[(size_t)p * (HW/2)];            // row gy0
        float2 c = kp[(size_t)p * (HW/2) + W/2];      // row gy0+1
        wv0[p] = pack2(a.x, a.y);
        wv1[p] = pack2(c.x, c.y);
        m00 = fmaxf(m00, a.x); m01 = fmaxf(m01, a.y);
        m10 = fmaxf(m10, c.x); m11 = fmaxf(m11, c.y);
    }
    float s00 = 0.f, s01 = 0.f, s10 = 0.f, s11 = 0.f;
    #pragma unroll
    for (int p = 0; p < KK; ++p) {
        float a0 = __expf(lo2(wv0[p]) - m00), a1 = __expf(hi2(wv0[p]) - m01);
        float c0 = __expf(lo2(wv1[p]) - m10), c1 = __expf(hi2(wv1[p]) - m11);
        s00 += a0; s01 += a1; s10 += c0; s11 += c1;
        wv0[p] = pack2(a0, a1);
        wv1[p] = pack2(c0, c1);
    }
    {
        const float i00 = 1.f/s00, i01 = 1.f/s01, i10 = 1.f/s10, i11 = 1.f/s11;
        #pragma unroll
        for (int p = 0; p < KK; ++p) {
            wv0[p] = pack2(lo2(wv0[p]) * i00, hi2(wv0[p]) * i01);
            wv1[p] = pack2(lo2(wv1[p]) * i10, hi2(wv1[p]) * i11);
        }
    }

    float* obq = ob + (size_t)gy0 * W + gx0;
    const int qbase = (2*qy) * SCOLM + (2*qx + 2);   // slab window base (floats)

    // ---- per-warp channel pipeline: depth-3 prefetch, no block barriers ----
    for (int c = 0; c < C; ++c) {
        if      (c < C - 2) cp_wait<2>();    // channel c's group complete
        else if (c == C - 2) cp_wait<1>();
        else                 cp_wait<0>();
        __syncwarp();                         // cross-lane visibility of slab writes

        const float* t = slab_w + (c & (NBUF-1)) * SLAB_F + qbase;
        ull   a0 = 0, a1 = 0;                              // packed even-tap chains
        float e00 = 0.f, e01 = 0.f, e10 = 0.f, e11 = 0.f;  // scalar odd-tap chains
        #pragma unroll
        for (int dr = 0; dr < 6; ++dr) {
            const ull* rp = (const ull*)(t + dr * SCOLM);  // 8B aligned
            const ull L0 = rp[0], L1 = rp[1], L2 = rp[2];  // (d0,d1)(d2,d3)(d4,d5)
            if (dr <= 4) {
                const int pb = dr * KS;
                a0  = fma2(wv0[pb+0], L0, a0);
                a0  = fma2(wv0[pb+2], L1, a0);
                a0  = fma2(wv0[pb+4], L2, a0);
                e00 = fmaf(lo2(wv0[pb+1]), hi2(L0), e00);  // c0 += w1*d1
                e01 = fmaf(hi2(wv0[pb+1]), lo2(L1), e01);  // c1 += w1*d2
                e00 = fmaf(lo2(wv0[pb+3]), hi2(L1), e00);  // c0 += w3*d3
                e01 = fmaf(hi2(wv0[pb+3]), lo2(L2), e01);  // c1 += w3*d4
            }
            if (dr >= 1) {
                const int pb = (dr - 1) * KS;
                a1  = fma2(wv1[pb+0], L0, a1);
                a1  = fma2(wv1[pb+2], L1, a1);
                a1  = fma2(wv1[pb+4], L2, a1);
                e10 = fmaf(lo2(wv1[pb+1]), hi2(L0), e10);
                e11 = fmaf(hi2(wv1[pb+1]), lo2(L1), e11);
                e10 = fmaf(lo2(wv1[pb+3]), hi2(L1), e10);
                e11 = fmaf(hi2(wv1[pb+3]), lo2(L2), e11);
            }
        }
        float* o = obq + (size_t)c * HW;
        *(ull*)(o)     = pack2(lo2(a0) + e00, hi2(a0) + e01);   // STG.64 row gy0
        *(ull*)(o + W) = pack2(lo2(a1) + e10, hi2(a1) + e11);   // STG.64 row gy0+1

        // prefetch channel c+3 into ring slot (c+3)&3 (last read at iter c-1)
        if (c + PREF < C) {
            const float* src = xb + (size_t)(c + PREF) * HW;
            const uint32_t db = sbase + (uint32_t)((c + PREF) & (NBUF-1)) * SLAB_B;
            #pragma unroll
            for (int j = 0; j < PREF; ++j) {
                if (is16[j]) cp_async16(db + doff[j], src + soff[j]);
                else         cp_async4 (db + doff[j], src + soff[j]);
            }
        }
        cp_commit();   // unconditional: keeps group accounting uniform (empty groups ok)
    }
}

extern "C" void kernel_launch(void* const* d_in, const int* in_sizes, int n_in,
                              void* d_out, int out_size)
{
    const float* x    = (const float*)d_in[0];
    const float* kern = (const float*)d_in[1];
    float*       out  = (float*)d_out;

    dim3 grid(W / 32, H / 16, B);   // (8,16,4) = 512 blocks, 4 warps each
    dds_kernel<<<grid, NTHREADS>>>(x, kern, out);
}